// round 14
// baseline (speedup 1.0000x reference)
#include <cuda_runtime.h>
#include <cuda_fp16.h>
#include <cstdint>

// out[n,d] = sum_m softmax_m( w2 . tanh(x[m,n,:] @ W1 + b1) ) * x[m,n,d]
// M=8, N=100000, D=256, H=128.
// Per CTA: 4 nodes x 8 metapaths = 32 GEMM rows, 128 threads (4 warps),
// warp tile 32 rows x 32 cols. A tile fp16 in smem (MMA operand AND
// weighted-sum source). B (W1) pre-baked as ldmatrix-fragment image in
// global, pinned in L1 (evict_last); A streams via .cs. 8 CTAs/SM.
// Softmax fully in-warp via butterfly shuffles (no 2nd barrier).

constexpr int TN  = 4;
constexpr int NTH = 128;

// smem offsets from 1024B-aligned base
constexpr int SM_A    = 0;        // 16384 B : A tile fp16 [32 rows][256 k], swizzled
constexpr int SM_PART = 16384;    //   512 B : logit partials [32][4]
constexpr int SM_B1   = 16896;    //   512 B
constexpr int SM_W2   = 17408;    //   512 B
constexpr int SM_BYTES = 17920 + 1024;

// A swizzle: 512B rows; XOR byte bits[4:6] with row&7  (row = b>>9)
__host__ __device__ __forceinline__ int swA(int b) { return b ^ (((b >> 9) & 7) << 4); }
// W1 staging swizzle (prep kernel only)
__host__ __device__ __forceinline__ int swW(int b) { return b ^ (((b >> 8) & 7) << 4); }

// ---------------- asm helpers ------------------
__device__ __forceinline__ float lds32(uint32_t a) {
    float v; asm volatile("ld.shared.f32 %0, [%1];" : "=f"(v) : "r"(a)); return v;
}
__device__ __forceinline__ void sts32(uint32_t a, float v) {
    asm volatile("st.shared.f32 [%0], %1;" :: "r"(a), "f"(v) : "memory");
}
__device__ __forceinline__ float4 lds128(uint32_t a) {
    float4 v;
    asm volatile("ld.shared.v4.f32 {%0,%1,%2,%3}, [%4];"
                 : "=f"(v.x), "=f"(v.y), "=f"(v.z), "=f"(v.w) : "r"(a));
    return v;
}
__device__ __forceinline__ void sts64u(uint32_t a, uint2 v) {
    asm volatile("st.shared.v2.b32 [%0], {%1,%2};" :: "r"(a), "r"(v.x), "r"(v.y) : "memory");
}
__device__ __forceinline__ uint2 lds64u(uint32_t a) {
    uint2 v;
    asm volatile("ld.shared.v2.b32 {%0,%1}, [%2];" : "=r"(v.x), "=r"(v.y) : "r"(a));
    return v;
}
__device__ __forceinline__ void sts16h(uint32_t a, __half v) {
    asm volatile("st.shared.b16 [%0], %1;" :: "r"(a), "h"(*(unsigned short*)&v) : "memory");
}
__device__ __forceinline__ void stg128cs(float4* p, float4 v) {
    asm volatile("st.global.cs.v4.f32 [%0], {%1,%2,%3,%4};"
                 :: "l"(p), "f"(v.x), "f"(v.y), "f"(v.z), "f"(v.w) : "memory");
}
__device__ __forceinline__ float4 ldg128cs(const float4* p) {
    float4 v;
    asm volatile("ld.global.cs.v4.f32 {%0,%1,%2,%3}, [%4];"
                 : "=f"(v.x), "=f"(v.y), "=f"(v.z), "=f"(v.w) : "l"(p));
    return v;
}
__device__ __forceinline__ uint4 ldg128_nc_last(const uint4* p) {
    uint4 v;
    asm volatile("ld.global.nc.L1::evict_last.v4.u32 {%0,%1,%2,%3}, [%4];"
                 : "=r"(v.x), "=r"(v.y), "=r"(v.z), "=r"(v.w) : "l"(p));
    return v;
}
__device__ __forceinline__ uint4 ldmx4(uint32_t a) {
    uint4 r;
    asm volatile("ldmatrix.sync.aligned.m8n8.x4.shared.b16 {%0,%1,%2,%3}, [%4];"
                 : "=r"(r.x), "=r"(r.y), "=r"(r.z), "=r"(r.w) : "r"(a));
    return r;
}
__device__ __forceinline__ uint4 ldmx4t(uint32_t a) {
    uint4 r;
    asm volatile("ldmatrix.sync.aligned.m8n8.x4.trans.shared.b16 {%0,%1,%2,%3}, [%4];"
                 : "=r"(r.x), "=r"(r.y), "=r"(r.z), "=r"(r.w) : "r"(a));
    return r;
}
__device__ __forceinline__ void mma16816(float* c, uint32_t a0, uint32_t a1,
                                         uint32_t a2, uint32_t a3,
                                         uint32_t b0, uint32_t b1) {
    asm volatile("mma.sync.aligned.m16n8k16.row.col.f32.f16.f16.f32 "
                 "{%0,%1,%2,%3}, {%4,%5,%6,%7}, {%8,%9}, {%0,%1,%2,%3};"
                 : "+f"(c[0]), "+f"(c[1]), "+f"(c[2]), "+f"(c[3])
                 : "r"(a0), "r"(a1), "r"(a2), "r"(a3), "r"(b0), "r"(b1));
}
__device__ __forceinline__ uint32_t packh2(float lo, float hi) {
    __half2 h = __floats2half2_rn(lo, hi);
    return *reinterpret_cast<uint32_t*>(&h);
}
__device__ __forceinline__ float fast_tanh(float x) {
    float e = __expf(2.0f * x);
    return 1.0f - __fdividef(2.0f, e + 1.0f);
}

// ---- B fragment image: [set = ks*8+hc][lane 0..31] -> uint4 (64 KB) --------
__device__ __align__(16) uint4 g_w1frag[128 * 32];

__global__ void prep_w1frag_kernel(const float* __restrict__ W1) {
    extern __shared__ char smraw[];
    uint32_t raw;
    asm("{ .reg .u64 t; cvta.to.shared.u64 t, %1; cvt.u32.u64 %0, t; }"
        : "=r"(raw) : "l"(smraw));
    const uint32_t base = (raw + 1023u) & ~1023u;

    const int tid = threadIdx.x, wid = tid >> 5, lane = tid & 31;

    for (int idx = tid; idx < 256 * 128; idx += 512) {
        int d = idx >> 7, j = idx & 127;
        __half h = __float2half_rn(W1[idx]);
        sts16h(base + (uint32_t)swW(d * 256 + j * 2), h);
    }
    __syncthreads();

    const int lrow  = (lane & 7) + ((lane >> 3) & 1) * 8;
    const int bcol8 = ((lane >> 4) & 1) * 8;
    #pragma unroll
    for (int u = 0; u < 8; u++) {
        int s  = wid * 8 + u;        // set id 0..127
        int ks = s >> 3, hc = s & 7;
        uint32_t wAddr = base +
            (uint32_t)swW((ks * 16 + lrow) * 256 + (hc * 16 + bcol8) * 2);
        uint4 bb = ldmx4t(wAddr);
        g_w1frag[s * 32 + lane] = bb;
    }
}

// --------------------------------- main -----------------------------------
__global__ __launch_bounds__(NTH, 8)
void hete_kernel(const float* __restrict__ homo, const float* __restrict__ b1g,
                 const float* __restrict__ w2g, float* __restrict__ out, int Nn) {
    extern __shared__ char smraw[];
    uint32_t raw;
    asm("{ .reg .u64 t; cvta.to.shared.u64 t, %1; cvt.u32.u64 %0, t; }"
        : "=r"(raw) : "l"(smraw));
    const uint32_t base = (raw + 1023u) & ~1023u;

    const int tid = threadIdx.x, wid = tid >> 5, lane = tid & 31;
    const int n0 = blockIdx.x * TN;

    sts32(base + SM_B1 + tid * 4, b1g[tid]);
    sts32(base + SM_W2 + tid * 4, w2g[tid]);

    // A tile fp16: 32 rows x 512B, swA swizzle. 2048 float4 / 128 thr = 16
    // each, two batches of 8 outstanding streaming LDG.128 (MLP=8).
    {
        const float4* homo4 = (const float4*)homo;
        #pragma unroll 1
        for (int kk = 0; kk < 16; kk += 8) {
            float4 v[8];
            #pragma unroll
            for (int u = 0; u < 8; u++) {
                int idx = (kk + u) * NTH + tid;
                int row = idx >> 6, d4 = idx & 63;
                int m = row >> 2, i = row & 3;
                int n = n0 + i; if (n >= Nn) n = Nn - 1;
                v[u] = ldg128cs(homo4 + ((size_t)m * Nn + n) * 64 + d4);
            }
            #pragma unroll
            for (int u = 0; u < 8; u++) {
                int idx = (kk + u) * NTH + tid;
                int row = idx >> 6, d4 = idx & 63;
                uint2 p;
                p.x = packh2(v[u].x, v[u].y);
                p.y = packh2(v[u].z, v[u].w);
                sts64u(base + SM_A + swA(row * 512 + d4 * 8), p);
            }
        }
    }
    __syncthreads();

    // ---- GEMM: warp tile = 32 rows x 32 cols; hq = wid (0..3) --------------
    const int hq = wid;              // 32-col quarter of H
    const int gr = lane >> 2;        // fragment group row 0..7
    const int qk = (lane & 3) * 2;   // fragment col pair within 8

    float acc[32];                   // [rowtile 2][ntile 4][4]
    #pragma unroll
    for (int i = 0; i < 32; i++) acc[i] = 0.0f;

    const int arow0 = ((lane >> 3) & 1) * 8 + (lane & 7);
    const uint32_t aBase0 = base + SM_A + arow0 * 512;
    const uint32_t aBase1 = aBase0 + 16 * 512;
    const uint32_t aXor  = (uint32_t)((arow0 & 7) << 4);
    const uint32_t aK16  = (uint32_t)(((lane >> 4) & 1) * 16);
    const uint4* __restrict__ gB = g_w1frag + (hq * 2) * 32 + lane;

    // pipelined: b0 one iteration ahead; b1 loaded just before use
    uint4 b0 = ldg128_nc_last(gB);
    #pragma unroll
    for (int ks = 0; ks < 16; ks++) {
        uint32_t ko = (((uint32_t)ks * 32) + aK16) ^ aXor;
        uint4 a0 = ldmx4(aBase0 + ko);
        uint4 a1 = ldmx4(aBase1 + ko);
        uint4 b1 = ldg128_nc_last(gB + ks * 256 + 32);
        // set-0 MMAs (ntiles 0,1 of both rowtiles)
        mma16816(acc + 0,  a0.x, a0.y, a0.z, a0.w, b0.x, b0.y);
        mma16816(acc + 4,  a0.x, a0.y, a0.z, a0.w, b0.z, b0.w);
        mma16816(acc + 16, a1.x, a1.y, a1.z, a1.w, b0.x, b0.y);
        mma16816(acc + 20, a1.x, a1.y, a1.z, a1.w, b0.z, b0.w);
        // prefetch next iteration's set-0 while set-1 MMAs run
        uint4 b0n;
        if (ks < 15) b0n = ldg128_nc_last(gB + (ks + 1) * 256);
        mma16816(acc + 8,  a0.x, a0.y, a0.z, a0.w, b1.x, b1.y);
        mma16816(acc + 12, a0.x, a0.y, a0.z, a0.w, b1.z, b1.w);
        mma16816(acc + 24, a1.x, a1.y, a1.z, a1.w, b1.x, b1.y);
        mma16816(acc + 28, a1.x, a1.y, a1.z, a1.w, b1.z, b1.w);
        if (ks < 15) b0 = b0n;
    }

    // ---------------- logits: tanh + dot(w2), quad reduce -------------------
    {
        float b1a[4], b1b[4], w2a[4], w2b[4];
        #pragma unroll
        for (int t = 0; t < 4; t++) {
            int col = hq * 32 + t * 8 + qk;
            b1a[t] = lds32(base + SM_B1 + col * 4);
            b1b[t] = lds32(base + SM_B1 + col * 4 + 4);
            w2a[t] = lds32(base + SM_W2 + col * 4);
            w2b[t] = lds32(base + SM_W2 + col * 4 + 4);
        }
        #pragma unroll
        for (int rt = 0; rt < 2; rt++) {
            float s0 = 0.0f, s1 = 0.0f;
            #pragma unroll
            for (int t = 0; t < 4; t++) {
                const float* a = acc + rt * 16 + t * 4;
                s0 += fast_tanh(a[0] + b1a[t]) * w2a[t]
                    + fast_tanh(a[1] + b1b[t]) * w2b[t];
                s1 += fast_tanh(a[2] + b1a[t]) * w2a[t]
                    + fast_tanh(a[3] + b1b[t]) * w2b[t];
            }
            s0 += __shfl_xor_sync(0xffffffffu, s0, 1);
            s0 += __shfl_xor_sync(0xffffffffu, s0, 2);
            s1 += __shfl_xor_sync(0xffffffffu, s1, 1);
            s1 += __shfl_xor_sync(0xffffffffu, s1, 2);
            if ((lane & 3) == 0) {
                int r = rt * 16 + gr;
                sts32(base + SM_PART + (r * 4 + hq) * 4, s0);
                sts32(base + SM_PART + ((r + 8) * 4 + hq) * 4, s1);
            }
        }
    }
    __syncthreads();

    // ---- softmax over m, replicated per warp via butterfly shuffles --------
    // lane l holds row r = l = m*4+node  (m = l>>2, node = l&3)
    float att;
    {
        float4 pa = lds128(base + SM_PART + lane * 16);
        float s = pa.x + pa.y + pa.z + pa.w;
        float mx = s;
        mx = fmaxf(mx, __shfl_xor_sync(0xffffffffu, mx, 4));
        mx = fmaxf(mx, __shfl_xor_sync(0xffffffffu, mx, 8));
        mx = fmaxf(mx, __shfl_xor_sync(0xffffffffu, mx, 16));
        float e = __expf(s - mx);
        float ss = e;
        ss += __shfl_xor_sync(0xffffffffu, ss, 4);
        ss += __shfl_xor_sync(0xffffffffu, ss, 8);
        ss += __shfl_xor_sync(0xffffffffu, ss, 16);
        att = e * __fdividef(1.0f, ss);
    }

    // ------- weighted sum from fp16 A tile (1 warp per node, 2 halves) ------
    {
        int node = wid;                 // 0..3
        int n = n0 + node;
        float a[8];
        #pragma unroll
        for (int m = 0; m < 8; m++)
            a[m] = __shfl_sync(0xffffffffu, att, m * 4 + node);
        if (n < Nn) {
            #pragma unroll
            for (int half = 0; half < 2; half++) {
                int c2 = lane + 32 * half;      // 8-byte chunk 0..63
                float4 o = make_float4(0.f, 0.f, 0.f, 0.f);
                #pragma unroll
                for (int m = 0; m < 8; m++) {
                    int row = m * 4 + node;
                    uint2 rawv = lds64u(base + SM_A + swA(row * 512 + c2 * 8));
                    float2 f0 = __half22float2(*reinterpret_cast<__half2*>(&rawv.x));
                    float2 f1 = __half22float2(*reinterpret_cast<__half2*>(&rawv.y));
                    o.x += a[m] * f0.x; o.y += a[m] * f0.y;
                    o.z += a[m] * f1.x; o.w += a[m] * f1.y;
                }
                stg128cs(((float4*)out) + (size_t)n * 64 + c2, o);
            }
        }
    }
}

extern "C" void kernel_launch(void* const* d_in, const int* in_sizes, int n_in,
                              void* d_out, int out_size) {
    const float* homo = (const float*)d_in[1];
    const float* W1   = (const float*)d_in[2];
    const float* b1   = (const float*)d_in[3];
    const float* W2   = (const float*)d_in[4];
    // b2 is a scalar added to every logit -> cancels in softmax over m; ignored.
    int Nn = in_sizes[0];

    const int prepSmem = 66560;  // 64KB stage + align slack
    cudaFuncSetAttribute(prep_w1frag_kernel,
                         cudaFuncAttributeMaxDynamicSharedMemorySize, prepSmem);
    cudaFuncSetAttribute(hete_kernel, cudaFuncAttributeMaxDynamicSharedMemorySize, SM_BYTES);
    prep_w1frag_kernel<<<1, 512, prepSmem>>>(W1);
    int grid = (Nn + TN - 1) / TN;
    hete_kernel<<<grid, NTH, SM_BYTES>>>(homo, b1, W2, (float*)d_out, Nn);
}

// round 15
// speedup vs baseline: 1.0082x; 1.0082x over previous
#include <cuda_runtime.h>
#include <cuda_fp16.h>
#include <cstdint>

// out[n,d] = sum_m softmax_m( w2 . tanh(x[m,n,:] @ W1 + b1) ) * x[m,n,d]
// M=8, N=100000, D=256, H=128.
// Per CTA: 4 nodes x 8 metapaths = 32 GEMM rows, 128 threads (4 warps),
// warp tile 32 rows x 32 cols. A tile fp16 in smem (MMA operand AND
// weighted-sum source). B (W1) pre-baked as ldmatrix-fragment image in
// global, pinned in L1 (evict_last); A streams via .cs. 8 CTAs/SM.
// Round-13 GEMM loop (compiler-scheduled B loads) + in-warp shuffle softmax.

constexpr int TN  = 4;
constexpr int NTH = 128;

// smem offsets from 1024B-aligned base
constexpr int SM_A    = 0;        // 16384 B : A tile fp16 [32 rows][256 k], swizzled
constexpr int SM_PART = 16384;    //   512 B : logit partials [32][4]
constexpr int SM_B1   = 16896;    //   512 B
constexpr int SM_W2   = 17408;    //   512 B
constexpr int SM_BYTES = 17920 + 1024;

// A swizzle: 512B rows; XOR byte bits[4:6] with row&7  (row = b>>9)
__host__ __device__ __forceinline__ int swA(int b) { return b ^ (((b >> 9) & 7) << 4); }
// W1 staging swizzle (prep kernel only)
__host__ __device__ __forceinline__ int swW(int b) { return b ^ (((b >> 8) & 7) << 4); }

// ---------------- asm helpers ------------------
__device__ __forceinline__ float lds32(uint32_t a) {
    float v; asm volatile("ld.shared.f32 %0, [%1];" : "=f"(v) : "r"(a)); return v;
}
__device__ __forceinline__ void sts32(uint32_t a, float v) {
    asm volatile("st.shared.f32 [%0], %1;" :: "r"(a), "f"(v) : "memory");
}
__device__ __forceinline__ float4 lds128(uint32_t a) {
    float4 v;
    asm volatile("ld.shared.v4.f32 {%0,%1,%2,%3}, [%4];"
                 : "=f"(v.x), "=f"(v.y), "=f"(v.z), "=f"(v.w) : "r"(a));
    return v;
}
__device__ __forceinline__ void sts64u(uint32_t a, uint2 v) {
    asm volatile("st.shared.v2.b32 [%0], {%1,%2};" :: "r"(a), "r"(v.x), "r"(v.y) : "memory");
}
__device__ __forceinline__ uint2 lds64u(uint32_t a) {
    uint2 v;
    asm volatile("ld.shared.v2.b32 {%0,%1}, [%2];" : "=r"(v.x), "=r"(v.y) : "r"(a));
    return v;
}
__device__ __forceinline__ void sts16h(uint32_t a, __half v) {
    asm volatile("st.shared.b16 [%0], %1;" :: "r"(a), "h"(*(unsigned short*)&v) : "memory");
}
__device__ __forceinline__ void stg128cs(float4* p, float4 v) {
    asm volatile("st.global.cs.v4.f32 [%0], {%1,%2,%3,%4};"
                 :: "l"(p), "f"(v.x), "f"(v.y), "f"(v.z), "f"(v.w) : "memory");
}
__device__ __forceinline__ float4 ldg128cs(const float4* p) {
    float4 v;
    asm volatile("ld.global.cs.v4.f32 {%0,%1,%2,%3}, [%4];"
                 : "=f"(v.x), "=f"(v.y), "=f"(v.z), "=f"(v.w) : "l"(p));
    return v;
}
__device__ __forceinline__ uint4 ldg128_nc_last(const uint4* p) {
    uint4 v;
    asm volatile("ld.global.nc.L1::evict_last.v4.u32 {%0,%1,%2,%3}, [%4];"
                 : "=r"(v.x), "=r"(v.y), "=r"(v.z), "=r"(v.w) : "l"(p));
    return v;
}
__device__ __forceinline__ uint4 ldmx4(uint32_t a) {
    uint4 r;
    asm volatile("ldmatrix.sync.aligned.m8n8.x4.shared.b16 {%0,%1,%2,%3}, [%4];"
                 : "=r"(r.x), "=r"(r.y), "=r"(r.z), "=r"(r.w) : "r"(a));
    return r;
}
__device__ __forceinline__ uint4 ldmx4t(uint32_t a) {
    uint4 r;
    asm volatile("ldmatrix.sync.aligned.m8n8.x4.trans.shared.b16 {%0,%1,%2,%3}, [%4];"
                 : "=r"(r.x), "=r"(r.y), "=r"(r.z), "=r"(r.w) : "r"(a));
    return r;
}
__device__ __forceinline__ void mma16816(float* c, uint32_t a0, uint32_t a1,
                                         uint32_t a2, uint32_t a3,
                                         uint32_t b0, uint32_t b1) {
    asm volatile("mma.sync.aligned.m16n8k16.row.col.f32.f16.f16.f32 "
                 "{%0,%1,%2,%3}, {%4,%5,%6,%7}, {%8,%9}, {%0,%1,%2,%3};"
                 : "+f"(c[0]), "+f"(c[1]), "+f"(c[2]), "+f"(c[3])
                 : "r"(a0), "r"(a1), "r"(a2), "r"(a3), "r"(b0), "r"(b1));
}
__device__ __forceinline__ uint32_t packh2(float lo, float hi) {
    __half2 h = __floats2half2_rn(lo, hi);
    return *reinterpret_cast<uint32_t*>(&h);
}
__device__ __forceinline__ float fast_tanh(float x) {
    float e = __expf(2.0f * x);
    return 1.0f - __fdividef(2.0f, e + 1.0f);
}

// ---- B fragment image: [set = ks*8+hc][lane 0..31] -> uint4 (64 KB) --------
__device__ __align__(16) uint4 g_w1frag[128 * 32];

__global__ void prep_w1frag_kernel(const float* __restrict__ W1) {
    extern __shared__ char smraw[];
    uint32_t raw;
    asm("{ .reg .u64 t; cvta.to.shared.u64 t, %1; cvt.u32.u64 %0, t; }"
        : "=r"(raw) : "l"(smraw));
    const uint32_t base = (raw + 1023u) & ~1023u;

    const int tid = threadIdx.x, wid = tid >> 5, lane = tid & 31;

    for (int idx = tid; idx < 256 * 128; idx += 512) {
        int d = idx >> 7, j = idx & 127;
        __half h = __float2half_rn(W1[idx]);
        sts16h(base + (uint32_t)swW(d * 256 + j * 2), h);
    }
    __syncthreads();

    const int lrow  = (lane & 7) + ((lane >> 3) & 1) * 8;
    const int bcol8 = ((lane >> 4) & 1) * 8;
    #pragma unroll
    for (int u = 0; u < 8; u++) {
        int s  = wid * 8 + u;        // set id 0..127
        int ks = s >> 3, hc = s & 7;
        uint32_t wAddr = base +
            (uint32_t)swW((ks * 16 + lrow) * 256 + (hc * 16 + bcol8) * 2);
        uint4 bb = ldmx4t(wAddr);
        g_w1frag[s * 32 + lane] = bb;
    }
}

// --------------------------------- main -----------------------------------
__global__ __launch_bounds__(NTH, 8)
void hete_kernel(const float* __restrict__ homo, const float* __restrict__ b1g,
                 const float* __restrict__ w2g, float* __restrict__ out, int Nn) {
    extern __shared__ char smraw[];
    uint32_t raw;
    asm("{ .reg .u64 t; cvta.to.shared.u64 t, %1; cvt.u32.u64 %0, t; }"
        : "=r"(raw) : "l"(smraw));
    const uint32_t base = (raw + 1023u) & ~1023u;

    const int tid = threadIdx.x, wid = tid >> 5, lane = tid & 31;
    const int n0 = blockIdx.x * TN;

    sts32(base + SM_B1 + tid * 4, b1g[tid]);
    sts32(base + SM_W2 + tid * 4, w2g[tid]);

    // A tile fp16: 32 rows x 512B, swA swizzle. 2048 float4 / 128 thr = 16
    // each, two batches of 8 outstanding streaming LDG.128 (MLP=8).
    {
        const float4* homo4 = (const float4*)homo;
        #pragma unroll 1
        for (int kk = 0; kk < 16; kk += 8) {
            float4 v[8];
            #pragma unroll
            for (int u = 0; u < 8; u++) {
                int idx = (kk + u) * NTH + tid;
                int row = idx >> 6, d4 = idx & 63;
                int m = row >> 2, i = row & 3;
                int n = n0 + i; if (n >= Nn) n = Nn - 1;
                v[u] = ldg128cs(homo4 + ((size_t)m * Nn + n) * 64 + d4);
            }
            #pragma unroll
            for (int u = 0; u < 8; u++) {
                int idx = (kk + u) * NTH + tid;
                int row = idx >> 6, d4 = idx & 63;
                uint2 p;
                p.x = packh2(v[u].x, v[u].y);
                p.y = packh2(v[u].z, v[u].w);
                sts64u(base + SM_A + swA(row * 512 + d4 * 8), p);
            }
        }
    }
    __syncthreads();

    // ---- GEMM: warp tile = 32 rows x 32 cols; hq = wid (0..3) --------------
    const int hq = wid;              // 32-col quarter of H
    const int gr = lane >> 2;        // fragment group row 0..7
    const int qk = (lane & 3) * 2;   // fragment col pair within 8

    float acc[32];                   // [rowtile 2][ntile 4][4]
    #pragma unroll
    for (int i = 0; i < 32; i++) acc[i] = 0.0f;

    const int arow0 = ((lane >> 3) & 1) * 8 + (lane & 7);
    const uint32_t aBase0 = base + SM_A + arow0 * 512;
    const uint32_t aBase1 = aBase0 + 16 * 512;
    const uint32_t aXor  = (uint32_t)((arow0 & 7) << 4);
    const uint32_t aK16  = (uint32_t)(((lane >> 4) & 1) * 16);
    const uint4* __restrict__ gB = g_w1frag + (hq * 2) * 32 + lane;

    #pragma unroll
    for (int ks = 0; ks < 16; ks++) {
        uint4 b0 = ldg128_nc_last(gB + ks * 256);
        uint4 b1 = ldg128_nc_last(gB + ks * 256 + 32);
        uint32_t ko = (((uint32_t)ks * 32) + aK16) ^ aXor;
        uint4 a0 = ldmx4(aBase0 + ko);
        uint4 a1 = ldmx4(aBase1 + ko);
        mma16816(acc + 0,  a0.x, a0.y, a0.z, a0.w, b0.x, b0.y);
        mma16816(acc + 4,  a0.x, a0.y, a0.z, a0.w, b0.z, b0.w);
        mma16816(acc + 8,  a0.x, a0.y, a0.z, a0.w, b1.x, b1.y);
        mma16816(acc + 12, a0.x, a0.y, a0.z, a0.w, b1.z, b1.w);
        mma16816(acc + 16, a1.x, a1.y, a1.z, a1.w, b0.x, b0.y);
        mma16816(acc + 20, a1.x, a1.y, a1.z, a1.w, b0.z, b0.w);
        mma16816(acc + 24, a1.x, a1.y, a1.z, a1.w, b1.x, b1.y);
        mma16816(acc + 28, a1.x, a1.y, a1.z, a1.w, b1.z, b1.w);
    }

    // ---------------- logits: tanh + dot(w2), quad reduce -------------------
    {
        float b1a[4], b1b[4], w2a[4], w2b[4];
        #pragma unroll
        for (int t = 0; t < 4; t++) {
            int col = hq * 32 + t * 8 + qk;
            b1a[t] = lds32(base + SM_B1 + col * 4);
            b1b[t] = lds32(base + SM_B1 + col * 4 + 4);
            w2a[t] = lds32(base + SM_W2 + col * 4);
            w2b[t] = lds32(base + SM_W2 + col * 4 + 4);
        }
        #pragma unroll
        for (int rt = 0; rt < 2; rt++) {
            float s0 = 0.0f, s1 = 0.0f;
            #pragma unroll
            for (int t = 0; t < 4; t++) {
                const float* a = acc + rt * 16 + t * 4;
                s0 += fast_tanh(a[0] + b1a[t]) * w2a[t]
                    + fast_tanh(a[1] + b1b[t]) * w2b[t];
                s1 += fast_tanh(a[2] + b1a[t]) * w2a[t]
                    + fast_tanh(a[3] + b1b[t]) * w2b[t];
            }
            s0 += __shfl_xor_sync(0xffffffffu, s0, 1);
            s0 += __shfl_xor_sync(0xffffffffu, s0, 2);
            s1 += __shfl_xor_sync(0xffffffffu, s1, 1);
            s1 += __shfl_xor_sync(0xffffffffu, s1, 2);
            if ((lane & 3) == 0) {
                int r = rt * 16 + gr;
                sts32(base + SM_PART + (r * 4 + hq) * 4, s0);
                sts32(base + SM_PART + ((r + 8) * 4 + hq) * 4, s1);
            }
        }
    }
    __syncthreads();

    // ---- softmax over m, replicated per warp via butterfly shuffles --------
    // lane l holds row r = l = m*4+node  (m = l>>2, node = l&3)
    float att;
    {
        float4 pa = lds128(base + SM_PART + lane * 16);
        float s = pa.x + pa.y + pa.z + pa.w;
        float mx = s;
        mx = fmaxf(mx, __shfl_xor_sync(0xffffffffu, mx, 4));
        mx = fmaxf(mx, __shfl_xor_sync(0xffffffffu, mx, 8));
        mx = fmaxf(mx, __shfl_xor_sync(0xffffffffu, mx, 16));
        float e = __expf(s - mx);
        float ss = e;
        ss += __shfl_xor_sync(0xffffffffu, ss, 4);
        ss += __shfl_xor_sync(0xffffffffu, ss, 8);
        ss += __shfl_xor_sync(0xffffffffu, ss, 16);
        att = e * __fdividef(1.0f, ss);
    }

    // ------- weighted sum from fp16 A tile (1 warp per node, 2 halves) ------
    {
        int node = wid;                 // 0..3
        int n = n0 + node;
        float a[8];
        #pragma unroll
        for (int m = 0; m < 8; m++)
            a[m] = __shfl_sync(0xffffffffu, att, m * 4 + node);
        if (n < Nn) {
            #pragma unroll
            for (int half = 0; half < 2; half++) {
                int c2 = lane + 32 * half;      // 8-byte chunk 0..63
                float4 o = make_float4(0.f, 0.f, 0.f, 0.f);
                #pragma unroll
                for (int m = 0; m < 8; m++) {
                    int row = m * 4 + node;
                    uint2 rawv = lds64u(base + SM_A + swA(row * 512 + c2 * 8));
                    float2 f0 = __half22float2(*reinterpret_cast<__half2*>(&rawv.x));
                    float2 f1 = __half22float2(*reinterpret_cast<__half2*>(&rawv.y));
                    o.x += a[m] * f0.x; o.y += a[m] * f0.y;
                    o.z += a[m] * f1.x; o.w += a[m] * f1.y;
                }
                stg128cs(((float4*)out) + (size_t)n * 64 + c2, o);
            }
        }
    }
}

extern "C" void kernel_launch(void* const* d_in, const int* in_sizes, int n_in,
                              void* d_out, int out_size) {
    const float* homo = (const float*)d_in[1];
    const float* W1   = (const float*)d_in[2];
    const float* b1   = (const float*)d_in[3];
    const float* W2   = (const float*)d_in[4];
    // b2 is a scalar added to every logit -> cancels in softmax over m; ignored.
    int Nn = in_sizes[0];

    const int prepSmem = 66560;  // 64KB stage + align slack
    cudaFuncSetAttribute(prep_w1frag_kernel,
                         cudaFuncAttributeMaxDynamicSharedMemorySize, prepSmem);
    cudaFuncSetAttribute(hete_kernel, cudaFuncAttributeMaxDynamicSharedMemorySize, SM_BYTES);
    prep_w1frag_kernel<<<1, 512, prepSmem>>>(W1);
    int grid = (Nn + TN - 1) / TN;
    hete_kernel<<<grid, NTH, SM_BYTES>>>(homo, b1, W2, (float*)d_out, Nn);
}

// round 16
// speedup vs baseline: 1.0176x; 1.0094x over previous
#include <cuda_runtime.h>
#include <cuda_fp16.h>
#include <cstdint>

// out[n,d] = sum_m softmax_m( w2 . tanh(x[m,n,:] @ W1 + b1) ) * x[m,n,d]
// M=8, N=100000, D=256, H=128.
// Per CTA: 4 nodes x 8 metapaths = 32 GEMM rows, 128 threads (4 warps),
// warp tile 32 rows x 32 cols. A tile fp16 in smem (MMA operand AND
// weighted-sum source). B (W1) pre-baked as ldmatrix-fragment image in
// global, pinned in L1 (evict_last); A streams via .cs. 8 CTAs/SM.
// = round-13 kernel (best: 203us) + row-wide lds128 epilogue.

constexpr int TN  = 4;
constexpr int NTH = 128;

// smem offsets from 1024B-aligned base
constexpr int SM_A    = 0;        // 16384 B : A tile fp16 [32 rows][256 k], swizzled
constexpr int SM_PART = 16384;    //   512 B : logit partials [32][4]
constexpr int SM_ATT  = 16896;    //   128 B
constexpr int SM_B1   = 17024;    //   512 B
constexpr int SM_W2   = 17536;    //   512 B
constexpr int SM_BYTES = 18048 + 1024;

// A swizzle: 512B rows; XOR byte bits[4:6] with row&7  (row = b>>9)
__host__ __device__ __forceinline__ int swA(int b) { return b ^ (((b >> 9) & 7) << 4); }
// W1 staging swizzle (prep kernel only)
__host__ __device__ __forceinline__ int swW(int b) { return b ^ (((b >> 8) & 7) << 4); }

// ---------------- asm helpers ------------------
__device__ __forceinline__ float lds32(uint32_t a) {
    float v; asm volatile("ld.shared.f32 %0, [%1];" : "=f"(v) : "r"(a)); return v;
}
__device__ __forceinline__ void sts32(uint32_t a, float v) {
    asm volatile("st.shared.f32 [%0], %1;" :: "r"(a), "f"(v) : "memory");
}
__device__ __forceinline__ float4 lds128(uint32_t a) {
    float4 v;
    asm volatile("ld.shared.v4.f32 {%0,%1,%2,%3}, [%4];"
                 : "=f"(v.x), "=f"(v.y), "=f"(v.z), "=f"(v.w) : "r"(a));
    return v;
}
__device__ __forceinline__ uint4 lds128u(uint32_t a) {
    uint4 v;
    asm volatile("ld.shared.v4.b32 {%0,%1,%2,%3}, [%4];"
                 : "=r"(v.x), "=r"(v.y), "=r"(v.z), "=r"(v.w) : "r"(a));
    return v;
}
__device__ __forceinline__ void sts64u(uint32_t a, uint2 v) {
    asm volatile("st.shared.v2.b32 [%0], {%1,%2};" :: "r"(a), "r"(v.x), "r"(v.y) : "memory");
}
__device__ __forceinline__ void sts16h(uint32_t a, __half v) {
    asm volatile("st.shared.b16 [%0], %1;" :: "r"(a), "h"(*(unsigned short*)&v) : "memory");
}
__device__ __forceinline__ void stg128cs(float4* p, float4 v) {
    asm volatile("st.global.cs.v4.f32 [%0], {%1,%2,%3,%4};"
                 :: "l"(p), "f"(v.x), "f"(v.y), "f"(v.z), "f"(v.w) : "memory");
}
__device__ __forceinline__ float4 ldg128cs(const float4* p) {
    float4 v;
    asm volatile("ld.global.cs.v4.f32 {%0,%1,%2,%3}, [%4];"
                 : "=f"(v.x), "=f"(v.y), "=f"(v.z), "=f"(v.w) : "l"(p));
    return v;
}
__device__ __forceinline__ uint4 ldg128_nc_last(const uint4* p) {
    uint4 v;
    asm volatile("ld.global.nc.L1::evict_last.v4.u32 {%0,%1,%2,%3}, [%4];"
                 : "=r"(v.x), "=r"(v.y), "=r"(v.z), "=r"(v.w) : "l"(p));
    return v;
}
__device__ __forceinline__ uint4 ldmx4(uint32_t a) {
    uint4 r;
    asm volatile("ldmatrix.sync.aligned.m8n8.x4.shared.b16 {%0,%1,%2,%3}, [%4];"
                 : "=r"(r.x), "=r"(r.y), "=r"(r.z), "=r"(r.w) : "r"(a));
    return r;
}
__device__ __forceinline__ uint4 ldmx4t(uint32_t a) {
    uint4 r;
    asm volatile("ldmatrix.sync.aligned.m8n8.x4.trans.shared.b16 {%0,%1,%2,%3}, [%4];"
                 : "=r"(r.x), "=r"(r.y), "=r"(r.z), "=r"(r.w) : "r"(a));
    return r;
}
__device__ __forceinline__ void mma16816(float* c, uint32_t a0, uint32_t a1,
                                         uint32_t a2, uint32_t a3,
                                         uint32_t b0, uint32_t b1) {
    asm volatile("mma.sync.aligned.m16n8k16.row.col.f32.f16.f16.f32 "
                 "{%0,%1,%2,%3}, {%4,%5,%6,%7}, {%8,%9}, {%0,%1,%2,%3};"
                 : "+f"(c[0]), "+f"(c[1]), "+f"(c[2]), "+f"(c[3])
                 : "r"(a0), "r"(a1), "r"(a2), "r"(a3), "r"(b0), "r"(b1));
}
__device__ __forceinline__ uint32_t packh2(float lo, float hi) {
    __half2 h = __floats2half2_rn(lo, hi);
    return *reinterpret_cast<uint32_t*>(&h);
}
__device__ __forceinline__ float fast_tanh(float x) {
    float e = __expf(2.0f * x);
    return 1.0f - __fdividef(2.0f, e + 1.0f);
}

// ---- B fragment image: [set = ks*8+hc][lane 0..31] -> uint4 (64 KB) --------
__device__ __align__(16) uint4 g_w1frag[128 * 32];

__global__ void prep_w1frag_kernel(const float* __restrict__ W1) {
    extern __shared__ char smraw[];
    uint32_t raw;
    asm("{ .reg .u64 t; cvta.to.shared.u64 t, %1; cvt.u32.u64 %0, t; }"
        : "=r"(raw) : "l"(smraw));
    const uint32_t base = (raw + 1023u) & ~1023u;

    const int tid = threadIdx.x, wid = tid >> 5, lane = tid & 31;

    for (int idx = tid; idx < 256 * 128; idx += 512) {
        int d = idx >> 7, j = idx & 127;
        __half h = __float2half_rn(W1[idx]);
        sts16h(base + (uint32_t)swW(d * 256 + j * 2), h);
    }
    __syncthreads();

    const int lrow  = (lane & 7) + ((lane >> 3) & 1) * 8;
    const int bcol8 = ((lane >> 4) & 1) * 8;
    #pragma unroll
    for (int u = 0; u < 8; u++) {
        int s  = wid * 8 + u;        // set id 0..127
        int ks = s >> 3, hc = s & 7;
        uint32_t wAddr = base +
            (uint32_t)swW((ks * 16 + lrow) * 256 + (hc * 16 + bcol8) * 2);
        uint4 bb = ldmx4t(wAddr);
        g_w1frag[s * 32 + lane] = bb;
    }
}

// --------------------------------- main -----------------------------------
__global__ __launch_bounds__(NTH, 8)
void hete_kernel(const float* __restrict__ homo, const float* __restrict__ b1g,
                 const float* __restrict__ w2g, float* __restrict__ out, int Nn) {
    extern __shared__ char smraw[];
    uint32_t raw;
    asm("{ .reg .u64 t; cvta.to.shared.u64 t, %1; cvt.u32.u64 %0, t; }"
        : "=r"(raw) : "l"(smraw));
    const uint32_t base = (raw + 1023u) & ~1023u;

    const int tid = threadIdx.x, wid = tid >> 5, lane = tid & 31;
    const int n0 = blockIdx.x * TN;

    sts32(base + SM_B1 + tid * 4, b1g[tid]);
    sts32(base + SM_W2 + tid * 4, w2g[tid]);

    // A tile fp16: 32 rows x 512B, swA swizzle. 2048 float4 / 128 thr = 16
    // each, two batches of 8 outstanding streaming LDG.128 (MLP=8).
    {
        const float4* homo4 = (const float4*)homo;
        #pragma unroll 1
        for (int kk = 0; kk < 16; kk += 8) {
            float4 v[8];
            #pragma unroll
            for (int u = 0; u < 8; u++) {
                int idx = (kk + u) * NTH + tid;
                int row = idx >> 6, d4 = idx & 63;
                int m = row >> 2, i = row & 3;
                int n = n0 + i; if (n >= Nn) n = Nn - 1;
                v[u] = ldg128cs(homo4 + ((size_t)m * Nn + n) * 64 + d4);
            }
            #pragma unroll
            for (int u = 0; u < 8; u++) {
                int idx = (kk + u) * NTH + tid;
                int row = idx >> 6, d4 = idx & 63;
                uint2 p;
                p.x = packh2(v[u].x, v[u].y);
                p.y = packh2(v[u].z, v[u].w);
                sts64u(base + SM_A + swA(row * 512 + d4 * 8), p);
            }
        }
    }
    __syncthreads();

    // ---- GEMM: warp tile = 32 rows x 32 cols; hq = wid (0..3) --------------
    const int hq = wid;              // 32-col quarter of H
    const int gr = lane >> 2;        // fragment group row 0..7
    const int qk = (lane & 3) * 2;   // fragment col pair within 8

    float acc[32];                   // [rowtile 2][ntile 4][4]
    #pragma unroll
    for (int i = 0; i < 32; i++) acc[i] = 0.0f;

    const int arow0 = ((lane >> 3) & 1) * 8 + (lane & 7);
    const uint32_t aBase0 = base + SM_A + arow0 * 512;
    const uint32_t aBase1 = aBase0 + 16 * 512;
    const uint32_t aXor  = (uint32_t)((arow0 & 7) << 4);
    const uint32_t aK16  = (uint32_t)(((lane >> 4) & 1) * 16);
    const uint4* __restrict__ gB = g_w1frag + (hq * 2) * 32 + lane;

    #pragma unroll
    for (int ks = 0; ks < 16; ks++) {
        uint4 b0 = ldg128_nc_last(gB + ks * 256);
        uint4 b1 = ldg128_nc_last(gB + ks * 256 + 32);
        uint32_t ko = (((uint32_t)ks * 32) + aK16) ^ aXor;
        uint4 a0 = ldmx4(aBase0 + ko);
        uint4 a1 = ldmx4(aBase1 + ko);
        mma16816(acc + 0,  a0.x, a0.y, a0.z, a0.w, b0.x, b0.y);
        mma16816(acc + 4,  a0.x, a0.y, a0.z, a0.w, b0.z, b0.w);
        mma16816(acc + 8,  a0.x, a0.y, a0.z, a0.w, b1.x, b1.y);
        mma16816(acc + 12, a0.x, a0.y, a0.z, a0.w, b1.z, b1.w);
        mma16816(acc + 16, a1.x, a1.y, a1.z, a1.w, b0.x, b0.y);
        mma16816(acc + 20, a1.x, a1.y, a1.z, a1.w, b0.z, b0.w);
        mma16816(acc + 24, a1.x, a1.y, a1.z, a1.w, b1.x, b1.y);
        mma16816(acc + 28, a1.x, a1.y, a1.z, a1.w, b1.z, b1.w);
    }

    // ---------------- logits: tanh + dot(w2), quad reduce -------------------
    {
        float b1a[4], b1b[4], w2a[4], w2b[4];
        #pragma unroll
        for (int t = 0; t < 4; t++) {
            int col = hq * 32 + t * 8 + qk;
            b1a[t] = lds32(base + SM_B1 + col * 4);
            b1b[t] = lds32(base + SM_B1 + col * 4 + 4);
            w2a[t] = lds32(base + SM_W2 + col * 4);
            w2b[t] = lds32(base + SM_W2 + col * 4 + 4);
        }
        #pragma unroll
        for (int rt = 0; rt < 2; rt++) {
            float s0 = 0.0f, s1 = 0.0f;
            #pragma unroll
            for (int t = 0; t < 4; t++) {
                const float* a = acc + rt * 16 + t * 4;
                s0 += fast_tanh(a[0] + b1a[t]) * w2a[t]
                    + fast_tanh(a[1] + b1b[t]) * w2b[t];
                s1 += fast_tanh(a[2] + b1a[t]) * w2a[t]
                    + fast_tanh(a[3] + b1b[t]) * w2b[t];
            }
            s0 += __shfl_xor_sync(0xffffffffu, s0, 1);
            s0 += __shfl_xor_sync(0xffffffffu, s0, 2);
            s1 += __shfl_xor_sync(0xffffffffu, s1, 1);
            s1 += __shfl_xor_sync(0xffffffffu, s1, 2);
            if ((lane & 3) == 0) {
                int r = rt * 16 + gr;
                sts32(base + SM_PART + (r * 4 + hq) * 4, s0);
                sts32(base + SM_PART + ((r + 8) * 4 + hq) * 4, s1);
            }
        }
    }
    __syncthreads();

    // ---------------- softmax over m (4 threads, one per node) --------------
    if (tid < TN) {
        float lg[8]; float mx = -1e30f;
        #pragma unroll
        for (int m = 0; m < 8; m++) {
            int r = m * 4 + tid;
            float4 pa = lds128(base + SM_PART + r * 16);
            float s = pa.x + pa.y + pa.z + pa.w;
            lg[m] = s; mx = fmaxf(mx, s);
        }
        float ss = 0.0f;
        #pragma unroll
        for (int m = 0; m < 8; m++) { lg[m] = __expf(lg[m] - mx); ss += lg[m]; }
        float inv = __fdividef(1.0f, ss);
        #pragma unroll
        for (int m = 0; m < 8; m++) sts32(base + SM_ATT + (m * 4 + tid) * 4, lg[m] * inv);
    }
    __syncthreads();

    // ------- weighted sum from fp16 A tile: 1 warp per node, lane covers ----
    // 16B (8 fp16 d-values) of each 512B row -> 8 lds128 + 2 stg128 per lane.
    {
        int node = wid;                 // 0..3
        int n = n0 + node;
        if (n < Nn) {
            float a[8];
            #pragma unroll
            for (int m = 0; m < 8; m++) a[m] = lds32(base + SM_ATT + (m * 4 + node) * 4);
            float o[8];
            #pragma unroll
            for (int j = 0; j < 8; j++) o[j] = 0.0f;
            #pragma unroll
            for (int m = 0; m < 8; m++) {
                int row = m * 4 + node;
                uint4 rv = lds128u(base + SM_A + swA(row * 512 + lane * 16));
                float2 f0 = __half22float2(*reinterpret_cast<__half2*>(&rv.x));
                float2 f1 = __half22float2(*reinterpret_cast<__half2*>(&rv.y));
                float2 f2 = __half22float2(*reinterpret_cast<__half2*>(&rv.z));
                float2 f3 = __half22float2(*reinterpret_cast<__half2*>(&rv.w));
                o[0] += a[m] * f0.x; o[1] += a[m] * f0.y;
                o[2] += a[m] * f1.x; o[3] += a[m] * f1.y;
                o[4] += a[m] * f2.x; o[5] += a[m] * f2.y;
                o[6] += a[m] * f3.x; o[7] += a[m] * f3.y;
            }
            float4* dst = ((float4*)out) + (size_t)n * 64 + lane * 2;
            stg128cs(dst,     make_float4(o[0], o[1], o[2], o[3]));
            stg128cs(dst + 1, make_float4(o[4], o[5], o[6], o[7]));
        }
    }
}

extern "C" void kernel_launch(void* const* d_in, const int* in_sizes, int n_in,
                              void* d_out, int out_size) {
    const float* homo = (const float*)d_in[1];
    const float* W1   = (const float*)d_in[2];
    const float* b1   = (const float*)d_in[3];
    const float* W2   = (const float*)d_in[4];
    // b2 is a scalar added to every logit -> cancels in softmax over m; ignored.
    int Nn = in_sizes[0];

    const int prepSmem = 66560;  // 64KB stage + align slack
    cudaFuncSetAttribute(prep_w1frag_kernel,
                         cudaFuncAttributeMaxDynamicSharedMemorySize, prepSmem);
    cudaFuncSetAttribute(hete_kernel, cudaFuncAttributeMaxDynamicSharedMemorySize, SM_BYTES);
    prep_w1frag_kernel<<<1, 512, prepSmem>>>(W1);
    int grid = (Nn + TN - 1) / TN;
    hete_kernel<<<grid, NTH, SM_BYTES>>>(homo, b1, W2, (float*)d_out, Nn);
}

// round 17
// speedup vs baseline: 1.0489x; 1.0307x over previous
#include <cuda_runtime.h>
#include <cuda_fp16.h>
#include <cstdint>

// out[n,d] = sum_m softmax_m( w2 . tanh(x[m,n,:] @ W1 + b1) ) * x[m,n,d]
// M=8, N=100000, D=256, H=128.
// Per CTA: 4 nodes x 8 metapaths = 32 GEMM rows, 128 threads (4 warps),
// warp tile 32 rows x 32 cols. A tile fp16 in smem (MMA operand AND
// weighted-sum source). B (W1) pre-baked as ldmatrix-fragment image in
// global, pinned in L1 (evict_last); A streams via .cs. 8 CTAs/SM.
// = round-13 kernel (best: 203us) with HW tanh.approx in the logit phase.

constexpr int TN  = 4;
constexpr int NTH = 128;

// smem offsets from 1024B-aligned base
constexpr int SM_A    = 0;        // 16384 B : A tile fp16 [32 rows][256 k], swizzled
constexpr int SM_PART = 16384;    //   512 B : logit partials [32][4]
constexpr int SM_ATT  = 16896;    //   128 B
constexpr int SM_B1   = 17024;    //   512 B
constexpr int SM_W2   = 17536;    //   512 B
constexpr int SM_BYTES = 18048 + 1024;

// A swizzle: 512B rows; XOR byte bits[4:6] with row&7  (row = b>>9)
__host__ __device__ __forceinline__ int swA(int b) { return b ^ (((b >> 9) & 7) << 4); }
// W1 staging swizzle (prep kernel only)
__host__ __device__ __forceinline__ int swW(int b) { return b ^ (((b >> 8) & 7) << 4); }

// ---------------- asm helpers ------------------
__device__ __forceinline__ float lds32(uint32_t a) {
    float v; asm volatile("ld.shared.f32 %0, [%1];" : "=f"(v) : "r"(a)); return v;
}
__device__ __forceinline__ void sts32(uint32_t a, float v) {
    asm volatile("st.shared.f32 [%0], %1;" :: "r"(a), "f"(v) : "memory");
}
__device__ __forceinline__ float4 lds128(uint32_t a) {
    float4 v;
    asm volatile("ld.shared.v4.f32 {%0,%1,%2,%3}, [%4];"
                 : "=f"(v.x), "=f"(v.y), "=f"(v.z), "=f"(v.w) : "r"(a));
    return v;
}
__device__ __forceinline__ void sts64u(uint32_t a, uint2 v) {
    asm volatile("st.shared.v2.b32 [%0], {%1,%2};" :: "r"(a), "r"(v.x), "r"(v.y) : "memory");
}
__device__ __forceinline__ uint2 lds64u(uint32_t a) {
    uint2 v;
    asm volatile("ld.shared.v2.b32 {%0,%1}, [%2];" : "=r"(v.x), "=r"(v.y) : "r"(a));
    return v;
}
__device__ __forceinline__ void sts16h(uint32_t a, __half v) {
    asm volatile("st.shared.b16 [%0], %1;" :: "r"(a), "h"(*(unsigned short*)&v) : "memory");
}
__device__ __forceinline__ void stg128cs(float4* p, float4 v) {
    asm volatile("st.global.cs.v4.f32 [%0], {%1,%2,%3,%4};"
                 :: "l"(p), "f"(v.x), "f"(v.y), "f"(v.z), "f"(v.w) : "memory");
}
__device__ __forceinline__ float4 ldg128cs(const float4* p) {
    float4 v;
    asm volatile("ld.global.cs.v4.f32 {%0,%1,%2,%3}, [%4];"
                 : "=f"(v.x), "=f"(v.y), "=f"(v.z), "=f"(v.w) : "l"(p));
    return v;
}
__device__ __forceinline__ uint4 ldg128_nc_last(const uint4* p) {
    uint4 v;
    asm volatile("ld.global.nc.L1::evict_last.v4.u32 {%0,%1,%2,%3}, [%4];"
                 : "=r"(v.x), "=r"(v.y), "=r"(v.z), "=r"(v.w) : "l"(p));
    return v;
}
__device__ __forceinline__ uint4 ldmx4(uint32_t a) {
    uint4 r;
    asm volatile("ldmatrix.sync.aligned.m8n8.x4.shared.b16 {%0,%1,%2,%3}, [%4];"
                 : "=r"(r.x), "=r"(r.y), "=r"(r.z), "=r"(r.w) : "r"(a));
    return r;
}
__device__ __forceinline__ uint4 ldmx4t(uint32_t a) {
    uint4 r;
    asm volatile("ldmatrix.sync.aligned.m8n8.x4.trans.shared.b16 {%0,%1,%2,%3}, [%4];"
                 : "=r"(r.x), "=r"(r.y), "=r"(r.z), "=r"(r.w) : "r"(a));
    return r;
}
__device__ __forceinline__ void mma16816(float* c, uint32_t a0, uint32_t a1,
                                         uint32_t a2, uint32_t a3,
                                         uint32_t b0, uint32_t b1) {
    asm volatile("mma.sync.aligned.m16n8k16.row.col.f32.f16.f16.f32 "
                 "{%0,%1,%2,%3}, {%4,%5,%6,%7}, {%8,%9}, {%0,%1,%2,%3};"
                 : "+f"(c[0]), "+f"(c[1]), "+f"(c[2]), "+f"(c[3])
                 : "r"(a0), "r"(a1), "r"(a2), "r"(a3), "r"(b0), "r"(b1));
}
__device__ __forceinline__ uint32_t packh2(float lo, float hi) {
    __half2 h = __floats2half2_rn(lo, hi);
    return *reinterpret_cast<uint32_t*>(&h);
}
// HW tanh (MUFU.TANH, sm_75+): single op vs exp+rcp chain
__device__ __forceinline__ float fast_tanh(float x) {
    float y;
    asm("tanh.approx.f32 %0, %1;" : "=f"(y) : "f"(x));
    return y;
}

// ---- B fragment image: [set = ks*8+hc][lane 0..31] -> uint4 (64 KB) --------
__device__ __align__(16) uint4 g_w1frag[128 * 32];

__global__ void prep_w1frag_kernel(const float* __restrict__ W1) {
    extern __shared__ char smraw[];
    uint32_t raw;
    asm("{ .reg .u64 t; cvta.to.shared.u64 t, %1; cvt.u32.u64 %0, t; }"
        : "=r"(raw) : "l"(smraw));
    const uint32_t base = (raw + 1023u) & ~1023u;

    const int tid = threadIdx.x, wid = tid >> 5, lane = tid & 31;

    for (int idx = tid; idx < 256 * 128; idx += 512) {
        int d = idx >> 7, j = idx & 127;
        __half h = __float2half_rn(W1[idx]);
        sts16h(base + (uint32_t)swW(d * 256 + j * 2), h);
    }
    __syncthreads();

    const int lrow  = (lane & 7) + ((lane >> 3) & 1) * 8;
    const int bcol8 = ((lane >> 4) & 1) * 8;
    #pragma unroll
    for (int u = 0; u < 8; u++) {
        int s  = wid * 8 + u;        // set id 0..127
        int ks = s >> 3, hc = s & 7;
        uint32_t wAddr = base +
            (uint32_t)swW((ks * 16 + lrow) * 256 + (hc * 16 + bcol8) * 2);
        uint4 bb = ldmx4t(wAddr);
        g_w1frag[s * 32 + lane] = bb;
    }
}

// --------------------------------- main -----------------------------------
__global__ __launch_bounds__(NTH, 8)
void hete_kernel(const float* __restrict__ homo, const float* __restrict__ b1g,
                 const float* __restrict__ w2g, float* __restrict__ out, int Nn) {
    extern __shared__ char smraw[];
    uint32_t raw;
    asm("{ .reg .u64 t; cvta.to.shared.u64 t, %1; cvt.u32.u64 %0, t; }"
        : "=r"(raw) : "l"(smraw));
    const uint32_t base = (raw + 1023u) & ~1023u;

    const int tid = threadIdx.x, wid = tid >> 5, lane = tid & 31;
    const int n0 = blockIdx.x * TN;

    sts32(base + SM_B1 + tid * 4, b1g[tid]);
    sts32(base + SM_W2 + tid * 4, w2g[tid]);

    // A tile fp16: 32 rows x 512B, swA swizzle. 2048 float4 / 128 thr = 16
    // each, two batches of 8 outstanding streaming LDG.128 (MLP=8).
    {
        const float4* homo4 = (const float4*)homo;
        #pragma unroll 1
        for (int kk = 0; kk < 16; kk += 8) {
            float4 v[8];
            #pragma unroll
            for (int u = 0; u < 8; u++) {
                int idx = (kk + u) * NTH + tid;
                int row = idx >> 6, d4 = idx & 63;
                int m = row >> 2, i = row & 3;
                int n = n0 + i; if (n >= Nn) n = Nn - 1;
                v[u] = ldg128cs(homo4 + ((size_t)m * Nn + n) * 64 + d4);
            }
            #pragma unroll
            for (int u = 0; u < 8; u++) {
                int idx = (kk + u) * NTH + tid;
                int row = idx >> 6, d4 = idx & 63;
                uint2 p;
                p.x = packh2(v[u].x, v[u].y);
                p.y = packh2(v[u].z, v[u].w);
                sts64u(base + SM_A + swA(row * 512 + d4 * 8), p);
            }
        }
    }
    __syncthreads();

    // ---- GEMM: warp tile = 32 rows x 32 cols; hq = wid (0..3) --------------
    const int hq = wid;              // 32-col quarter of H
    const int gr = lane >> 2;        // fragment group row 0..7
    const int qk = (lane & 3) * 2;   // fragment col pair within 8

    float acc[32];                   // [rowtile 2][ntile 4][4]
    #pragma unroll
    for (int i = 0; i < 32; i++) acc[i] = 0.0f;

    const int arow0 = ((lane >> 3) & 1) * 8 + (lane & 7);
    const uint32_t aBase0 = base + SM_A + arow0 * 512;
    const uint32_t aBase1 = aBase0 + 16 * 512;
    const uint32_t aXor  = (uint32_t)((arow0 & 7) << 4);
    const uint32_t aK16  = (uint32_t)(((lane >> 4) & 1) * 16);
    const uint4* __restrict__ gB = g_w1frag + (hq * 2) * 32 + lane;

    #pragma unroll
    for (int ks = 0; ks < 16; ks++) {
        uint4 b0 = ldg128_nc_last(gB + ks * 256);
        uint4 b1 = ldg128_nc_last(gB + ks * 256 + 32);
        uint32_t ko = (((uint32_t)ks * 32) + aK16) ^ aXor;
        uint4 a0 = ldmx4(aBase0 + ko);
        uint4 a1 = ldmx4(aBase1 + ko);
        mma16816(acc + 0,  a0.x, a0.y, a0.z, a0.w, b0.x, b0.y);
        mma16816(acc + 4,  a0.x, a0.y, a0.z, a0.w, b0.z, b0.w);
        mma16816(acc + 8,  a0.x, a0.y, a0.z, a0.w, b1.x, b1.y);
        mma16816(acc + 12, a0.x, a0.y, a0.z, a0.w, b1.z, b1.w);
        mma16816(acc + 16, a1.x, a1.y, a1.z, a1.w, b0.x, b0.y);
        mma16816(acc + 20, a1.x, a1.y, a1.z, a1.w, b0.z, b0.w);
        mma16816(acc + 24, a1.x, a1.y, a1.z, a1.w, b1.x, b1.y);
        mma16816(acc + 28, a1.x, a1.y, a1.z, a1.w, b1.z, b1.w);
    }

    // ---------------- logits: tanh + dot(w2), quad reduce -------------------
    {
        float b1a[4], b1b[4], w2a[4], w2b[4];
        #pragma unroll
        for (int t = 0; t < 4; t++) {
            int col = hq * 32 + t * 8 + qk;
            b1a[t] = lds32(base + SM_B1 + col * 4);
            b1b[t] = lds32(base + SM_B1 + col * 4 + 4);
            w2a[t] = lds32(base + SM_W2 + col * 4);
            w2b[t] = lds32(base + SM_W2 + col * 4 + 4);
        }
        #pragma unroll
        for (int rt = 0; rt < 2; rt++) {
            float s0 = 0.0f, s1 = 0.0f;
            #pragma unroll
            for (int t = 0; t < 4; t++) {
                const float* a = acc + rt * 16 + t * 4;
                s0 += fast_tanh(a[0] + b1a[t]) * w2a[t]
                    + fast_tanh(a[1] + b1b[t]) * w2b[t];
                s1 += fast_tanh(a[2] + b1a[t]) * w2a[t]
                    + fast_tanh(a[3] + b1b[t]) * w2b[t];
            }
            s0 += __shfl_xor_sync(0xffffffffu, s0, 1);
            s0 += __shfl_xor_sync(0xffffffffu, s0, 2);
            s1 += __shfl_xor_sync(0xffffffffu, s1, 1);
            s1 += __shfl_xor_sync(0xffffffffu, s1, 2);
            if ((lane & 3) == 0) {
                int r = rt * 16 + gr;
                sts32(base + SM_PART + (r * 4 + hq) * 4, s0);
                sts32(base + SM_PART + ((r + 8) * 4 + hq) * 4, s1);
            }
        }
    }
    __syncthreads();

    // ---------------- softmax over m (4 threads, one per node) --------------
    if (tid < TN) {
        float lg[8]; float mx = -1e30f;
        #pragma unroll
        for (int m = 0; m < 8; m++) {
            int r = m * 4 + tid;
            float4 pa = lds128(base + SM_PART + r * 16);
            float s = pa.x + pa.y + pa.z + pa.w;
            lg[m] = s; mx = fmaxf(mx, s);
        }
        float ss = 0.0f;
        #pragma unroll
        for (int m = 0; m < 8; m++) { lg[m] = __expf(lg[m] - mx); ss += lg[m]; }
        float inv = __fdividef(1.0f, ss);
        #pragma unroll
        for (int m = 0; m < 8; m++) sts32(base + SM_ATT + (m * 4 + tid) * 4, lg[m] * inv);
    }
    __syncthreads();

    // ------- weighted sum from fp16 A tile (1 warp per node, 2 halves) ------
    {
        int node = wid;                 // 0..3
        int n = n0 + node;
        if (n < Nn) {
            float a[8];
            #pragma unroll
            for (int m = 0; m < 8; m++) a[m] = lds32(base + SM_ATT + (m * 4 + node) * 4);
            #pragma unroll
            for (int half = 0; half < 2; half++) {
                int c2 = lane + 32 * half;      // 8-byte chunk 0..63
                float4 o = make_float4(0.f, 0.f, 0.f, 0.f);
                #pragma unroll
                for (int m = 0; m < 8; m++) {
                    int row = m * 4 + node;
                    uint2 rawv = lds64u(base + SM_A + swA(row * 512 + c2 * 8));
                    float2 f0 = __half22float2(*reinterpret_cast<__half2*>(&rawv.x));
                    float2 f1 = __half22float2(*reinterpret_cast<__half2*>(&rawv.y));
                    o.x += a[m] * f0.x; o.y += a[m] * f0.y;
                    o.z += a[m] * f1.x; o.w += a[m] * f1.y;
                }
                stg128cs(((float4*)out) + (size_t)n * 64 + c2, o);
            }
        }
    }
}

extern "C" void kernel_launch(void* const* d_in, const int* in_sizes, int n_in,
                              void* d_out, int out_size) {
    const float* homo = (const float*)d_in[1];
    const float* W1   = (const float*)d_in[2];
    const float* b1   = (const float*)d_in[3];
    const float* W2   = (const float*)d_in[4];
    // b2 is a scalar added to every logit -> cancels in softmax over m; ignored.
    int Nn = in_sizes[0];

    const int prepSmem = 66560;  // 64KB stage + align slack
    cudaFuncSetAttribute(prep_w1frag_kernel,
                         cudaFuncAttributeMaxDynamicSharedMemorySize, prepSmem);
    cudaFuncSetAttribute(hete_kernel, cudaFuncAttributeMaxDynamicSharedMemorySize, SM_BYTES);
    prep_w1frag_kernel<<<1, 512, prepSmem>>>(W1);
    int grid = (Nn + TN - 1) / TN;
    hete_kernel<<<grid, NTH, SM_BYTES>>>(homo, b1, W2, (float*)d_out, Nn);
}